// round 7
// baseline (speedup 1.0000x reference)
#include <cuda_runtime.h>
#include <cstdint>

#define B_SZ   32
#define RESN   100
#define ITERS  1000
#define KSPLIT 16

typedef unsigned long long ull;

// Jacobi tiling: 400 threads, each owns 5x5 cells in registers.
#define SLOTW  12                 // words per edge slot (48B -> conflict-free)
#define EDGEW  (400 * SLOTW)      // words per edge array (4800)
#define BUFW   (4 * EDGEW)        // words per buffer: top,bot,left,right (19200)

// -------- scratch (device globals; no allocation allowed) ----------
__device__ float g_h1[B_SZ * 128];
__device__ float g_h2[B_SZ * 256];
__device__ float g_h3[B_SZ * 512];
__device__ float g_part[KSPLIT * B_SZ * 10000];

// ---------------------- f32x2 helpers ------------------------------
__device__ __forceinline__ ull pack2(float lo, float hi) {
    ull r; unsigned a = __float_as_uint(lo), b = __float_as_uint(hi);
    asm("mov.b64 %0, {%1,%2};" : "=l"(r) : "r"(a), "r"(b));
    return r;
}
__device__ __forceinline__ float lo2(ull v) {
    unsigned a, b;
    asm("mov.b64 {%0,%1}, %2;" : "=r"(a), "=r"(b) : "l"(v));
    return __uint_as_float(a);
}
__device__ __forceinline__ float hi2(ull v) {
    unsigned a, b;
    asm("mov.b64 {%0,%1}, %2;" : "=r"(a), "=r"(b) : "l"(v));
    return __uint_as_float(b);
}
__device__ __forceinline__ ull shift_pair(ull a, ull b) {   // (hi a, lo b)
    unsigned a0, a1, b0, b1;
    asm("mov.b64 {%0,%1}, %2;" : "=r"(a0), "=r"(a1) : "l"(a));
    asm("mov.b64 {%0,%1}, %2;" : "=r"(b0), "=r"(b1) : "l"(b));
    ull r;
    asm("mov.b64 %0, {%1,%2};" : "=l"(r) : "r"(a1), "r"(b0));
    return r;
}
__device__ __forceinline__ ull fma2(ull a, ull b, ull c) {
    ull d;
    asm("fma.rn.f32x2 %0, %1, %2, %3;" : "=l"(d) : "l"(a), "l"(b), "l"(c));
    return d;
}
__device__ __forceinline__ ull mul2(ull a, ull b) {
    ull d;
    asm("mul.rn.f32x2 %0, %1, %2;" : "=l"(d) : "l"(a), "l"(b));
    return d;
}

// -------------------- MLP layers 1..3 (small) ----------------------
__global__ void fc1_kernel(const float* __restrict__ pores,
                           const float* __restrict__ W,
                           const float* __restrict__ bias) {
    int idx = blockIdx.x * blockDim.x + threadIdx.x;
    if (idx >= B_SZ * 128) return;
    int b = idx >> 7, j = idx & 127;
    float acc = bias[j];
#pragma unroll
    for (int k = 0; k < 25; k++)
        acc = fmaf(pores[b * 25 + k], W[k * 128 + j], acc);
    g_h1[idx] = fmaxf(acc, 0.0f);
}

__global__ void fc2_kernel(const float* __restrict__ W,
                           const float* __restrict__ bias) {
    int idx = blockIdx.x * blockDim.x + threadIdx.x;
    if (idx >= B_SZ * 256) return;
    int b = idx >> 8, j = idx & 255;
    float acc = bias[j];
#pragma unroll 8
    for (int k = 0; k < 128; k++)
        acc = fmaf(g_h1[b * 128 + k], W[k * 256 + j], acc);
    g_h2[idx] = fmaxf(acc, 0.0f);
}

__global__ void fc3_kernel(const float* __restrict__ W,
                           const float* __restrict__ bias) {
    int idx = blockIdx.x * blockDim.x + threadIdx.x;
    if (idx >= B_SZ * 512) return;
    int b = idx >> 9, j = idx & 511;
    float acc = bias[j];
#pragma unroll 8
    for (int k = 0; k < 256; k++)
        acc = fmaf(g_h2[b * 256 + k], W[k * 512 + j], acc);
    g_h3[idx] = fmaxf(acc, 0.0f);
}

// ---------------- fc4 stage 1: split-K partial sums ----------------
__global__ __launch_bounds__(128) void fc4_partial_kernel(
    const float* __restrict__ W)     // [512,10000]
{
    __shared__ float h3s[B_SZ * 32];
    int k0 = blockIdx.y * 32;
    for (int i = threadIdx.x; i < B_SZ * 32; i += blockDim.x) {
        int q = i >> 5, kk = i & 31;
        h3s[i] = g_h3[q * 512 + k0 + kk];
    }
    __syncthreads();

    int o = blockIdx.x * blockDim.x + threadIdx.x;
    if (o >= RESN * RESN) return;

    float acc[B_SZ];
#pragma unroll
    for (int q = 0; q < B_SZ; q++) acc[q] = 0.0f;

#pragma unroll
    for (int kk = 0; kk < 32; kk += 4) {
        float w0 = W[(k0 + kk + 0) * 10000 + o];
        float w1 = W[(k0 + kk + 1) * 10000 + o];
        float w2 = W[(k0 + kk + 2) * 10000 + o];
        float w3 = W[(k0 + kk + 3) * 10000 + o];
#pragma unroll
        for (int q = 0; q < B_SZ; q++) {
            acc[q] = fmaf(h3s[q * 32 + kk + 0], w0, acc[q]);
            acc[q] = fmaf(h3s[q * 32 + kk + 1], w1, acc[q]);
            acc[q] = fmaf(h3s[q * 32 + kk + 2], w2, acc[q]);
            acc[q] = fmaf(h3s[q * 32 + kk + 3], w3, acc[q]);
        }
    }

    float* dst = g_part + blockIdx.y * (B_SZ * 10000);
#pragma unroll
    for (int q = 0; q < B_SZ; q++)
        dst[q * 10000 + o] = acc[q];
}

// -------- fc4 stage 2: reduce + bias + residual + clamp ------------
__global__ __launch_bounds__(128) void fc4_final_kernel(
    const float* __restrict__ bias,
    const float* __restrict__ pores,
    float* __restrict__ cond)
{
    int o = blockIdx.x * blockDim.x + threadIdx.x;
    if (o >= RESN * RESN) return;
    int i = o / RESN, j = o % RESN;
    int pidx = (i / 20) * 5 + (j / 20);
    float bb = bias[o];
    int q0 = blockIdx.y * 4;
#pragma unroll
    for (int qq = 0; qq < 4; qq++) {
        int q = q0 + qq;
        float s = bb;
#pragma unroll
        for (int p = 0; p < KSPLIT; p++)
            s += g_part[p * (B_SZ * 10000) + q * 10000 + o];
        float base = 1.0f - pores[q * 25 + pidx];
        cond[q * 10000 + o] = fmaxf(s + base, 0.01f);
    }
}

// ---------- Jacobi: 5x5 register tiles, perimeter-only SMEM ----------
// 400 threads: band = tid/20 (row block), tcol = tid%20 (col block).
// Thread owns rows [5*band,5*band+5) x cols [5*tcol,5*tcol+5) as
// P0 (cols 0-1), P1 (cols 2-3) packed f32x2 + C4 scalar, per row.
// Per iteration only the tile perimeter moves through SMEM:
//   top/bottom row slots: 5 floats (as ull2 pair + scalar)
//   left/right col slots: 5 floats (as float4 + scalar)
// Slots are 12 words (48B): lane stride 48B mod 128B hits 8 distinct
// 16B groups -> conflict-free LDS.128/STS.128 phases.
__global__ __launch_bounds__(400, 1)
void jacobi_kernel(const float* __restrict__ cond,   // [32,10000]
                   float* __restrict__ kappa)        // [32]
{
    extern __shared__ float sm[];
    float* partial = sm + 2 * BUFW;    // 20 floats

    int b = blockIdx.x;
    const float* k = cond + b * 10000;
    int tid  = threadIdx.x;
    int band = tid / 20;
    int tcol = tid % 20;
    int r0 = band * 5, c0 = tcol * 5;

    const ull ONE2 = 0x3F8000003F800000ULL;

    ull  cN0[5], cN1[5], cS0[5], cS1[5], cW0[5], cW1[5], cE0[5], cE1[5];
    float cN4[5], cS4[5], cW4[5], cE4[5];
    ull  P0[5], P1[5];
    float C4[5];

    // ---- coefficients ----
#pragma unroll
    for (int i = 0; i < 5; i++) {
        int rg = r0 + i;
        int rm = (rg == 0)  ? 0  : rg - 1;
        int rp = (rg == 99) ? 99 : rg + 1;
        float fN[5], fS[5], fW[5], fE[5];
#pragma unroll
        for (int j = 0; j < 5; j++) {
            int c  = c0 + j;
            int cm = (c == 0)  ? 0  : c - 1;
            int cp = (c == 99) ? 99 : c + 1;
            float kc = k[rg * 100 + c];
            float kn = 0.5f * (kc + k[rm * 100 + c]);
            float ks = 0.5f * (kc + k[rp * 100 + c]);
            float kw = 0.5f * (kc + k[rg * 100 + cm]);
            float ke = 0.5f * (kc + k[rg * 100 + cp]);
            float inv = 1.0f / (kn + ks + kw + ke + 1e-12f);
            fN[j] = kn * inv; fS[j] = ks * inv;
            fW[j] = kw * inv; fE[j] = ke * inv;
        }
        cN0[i] = pack2(fN[0], fN[1]); cN1[i] = pack2(fN[2], fN[3]); cN4[i] = fN[4];
        cS0[i] = pack2(fS[0], fS[1]); cS1[i] = pack2(fS[2], fS[3]); cS4[i] = fS[4];
        cW0[i] = pack2(fW[0], fW[1]); cW1[i] = pack2(fW[2], fW[3]); cW4[i] = fW[4];
        cE0[i] = pack2(fE[0], fE[1]); cE1[i] = pack2(fE[2], fE[3]); cE4[i] = fE[4];
    }

    // ---- initial field + buffer-0 edges ----
    {
        float* topA = sm;
        float* botA = sm + EDGEW;
        float* lftA = sm + 2 * EDGEW;
        float* rgtA = sm + 3 * EDGEW;
#pragma unroll
        for (int i = 0; i < 5; i++) {
            float tv = 1.0f - (float)(r0 + i) * (1.0f / 99.0f);
            P0[i] = pack2(tv, tv); P1[i] = pack2(tv, tv); C4[i] = tv;
        }
        int so = tid * SLOTW;
        ulonglong2 t0; t0.x = P0[0]; t0.y = P1[0];
        *reinterpret_cast<ulonglong2*>(topA + so) = t0;
        topA[so + 4] = C4[0];
        ulonglong2 t4; t4.x = P0[4]; t4.y = P1[4];
        *reinterpret_cast<ulonglong2*>(botA + so) = t4;
        botA[so + 4] = C4[4];
        *reinterpret_cast<float4*>(lftA + so) =
            make_float4(lo2(P0[0]), lo2(P0[1]), lo2(P0[2]), lo2(P0[3]));
        lftA[so + 4] = lo2(P0[4]);
        *reinterpret_cast<float4*>(rgtA + so) =
            make_float4(C4[0], C4[1], C4[2], C4[3]);
        rgtA[so + 4] = C4[4];
    }
    __syncthreads();

    int cur = 0;
    for (int it = 0; it < ITERS; ++it) {
        float* bufC = sm + cur * BUFW;
        float* bufN = sm + (cur ^ 1) * BUFW;
        const float* topO = bufC;
        const float* botO = bufC + EDGEW;
        const float* lftO = bufC + 2 * EDGEW;
        const float* rgtO = bufC + 3 * EDGEW;
        float* topW = bufN;
        float* botW = bufN + EDGEW;
        float* lftW = bufN + 2 * EDGEW;
        float* rgtW = bufN + 3 * EDGEW;

        // ---- halo reads (OLD values); clamp addr, override value ----
        int nslot = ((band == 0)  ? tid : tid - 20) * SLOTW;
        int sslot = ((band == 19) ? tid : tid + 20) * SLOTW;
        int wslot = ((tcol == 0)  ? tid : tid - 1) * SLOTW;
        int eslot = ((tcol == 19) ? tid : tid + 1) * SLOTW;

        ulonglong2 nh = *reinterpret_cast<const ulonglong2*>(botO + nslot);
        float nh4 = botO[nslot + 4];
        ulonglong2 sh = *reinterpret_cast<const ulonglong2*>(topO + sslot);
        float sh4 = topO[sslot + 4];
        float4 wf = *reinterpret_cast<const float4*>(rgtO + wslot);
        float wf4 = rgtO[wslot + 4];
        float4 ef = *reinterpret_cast<const float4*>(lftO + eslot);
        float ef4 = lftO[eslot + 4];

        if (band == 0)  { nh.x = ONE2; nh.y = ONE2; nh4 = 1.0f; }
        if (band == 19) { sh.x = 0;    sh.y = 0;    sh4 = 0.0f; }
        float west[5] = {wf.x, wf.y, wf.z, wf.w, wf4};
        float east[5] = {ef.x, ef.y, ef.z, ef.w, ef4};

        ull pn0 = nh.x, pn1 = nh.y; float pn4 = nh4;
#pragma unroll
        for (int i = 0; i < 5; i++) {
            ull  o0 = P0[i], o1 = P1[i]; float o4 = C4[i];
            ull  s0, s1; float s4;
            if (i < 4) { s0 = P0[i + 1]; s1 = P1[i + 1]; s4 = C4[i + 1]; }
            else       { s0 = sh.x;      s1 = sh.y;      s4 = sh4; }
            float wv = (tcol == 0)  ? lo2(o0) : west[i];
            float ev = (tcol == 19) ? o4      : east[i];

            ull W0 = pack2(wv, lo2(o0));
            ull E0 = shift_pair(o0, o1);          // (c1, c2)
            ull E1 = pack2(hi2(o1), o4);

            ull t = mul2(cE0[i], E0);
            t = fma2(cW0[i], W0, t);
            t = fma2(cS0[i], s0, t);
            P0[i] = fma2(cN0[i], pn0, t);

            ull u = mul2(cE1[i], E1);
            u = fma2(cW1[i], E0, u);              // W-pair of P1 == E-pair of P0
            u = fma2(cS1[i], s1, u);
            P1[i] = fma2(cN1[i], pn1, u);

            float f = cE4[i] * ev;
            f = fmaf(cW4[i], hi2(o1), f);
            f = fmaf(cS4[i], s4, f);
            C4[i] = fmaf(cN4[i], pn4, f);

            pn0 = o0; pn1 = o1; pn4 = o4;
        }

        // ---- publish new perimeter ----
        int so = tid * SLOTW;
        ulonglong2 t0; t0.x = P0[0]; t0.y = P1[0];
        *reinterpret_cast<ulonglong2*>(topW + so) = t0;
        topW[so + 4] = C4[0];
        ulonglong2 t4; t4.x = P0[4]; t4.y = P1[4];
        *reinterpret_cast<ulonglong2*>(botW + so) = t4;
        botW[so + 4] = C4[4];
        *reinterpret_cast<float4*>(lftW + so) =
            make_float4(lo2(P0[0]), lo2(P0[1]), lo2(P0[2]), lo2(P0[3]));
        lftW[so + 4] = lo2(P0[4]);
        *reinterpret_cast<float4*>(rgtW + so) =
            make_float4(C4[0], C4[1], C4[2], C4[3]);
        rgtW[so + 4] = C4[4];

        __syncthreads();
        cur ^= 1;
    }

    // kappa = 2 * sum_c k[0,c] * (1 - T[0,c]); band-0 threads hold row 0
    if (band == 0) {
        float p = k[c0 + 0] * (1.0f - lo2(P0[0]))
                + k[c0 + 1] * (1.0f - hi2(P0[0]))
                + k[c0 + 2] * (1.0f - lo2(P1[0]))
                + k[c0 + 3] * (1.0f - hi2(P1[0]))
                + k[c0 + 4] * (1.0f - C4[0]);
        partial[tcol] = p;
    }
    __syncthreads();
    if (tid == 0) {
        float sum = 0.0f;
#pragma unroll
        for (int q = 0; q < 20; q++) sum += partial[q];
        kappa[b] = 2.0f * sum;
    }
}

// --------------------------- launcher ------------------------------
extern "C" void kernel_launch(void* const* d_in, const int* in_sizes, int n_in,
                              void* d_out, int out_size) {
    const float* pores = (const float*)d_in[0];
    const float* W1 = (const float*)d_in[1];
    const float* b1 = (const float*)d_in[2];
    const float* W2 = (const float*)d_in[3];
    const float* b2 = (const float*)d_in[4];
    const float* W3 = (const float*)d_in[5];
    const float* b3 = (const float*)d_in[6];
    const float* W4 = (const float*)d_in[7];
    const float* b4 = (const float*)d_in[8];

    float* out   = (float*)d_out;
    float* kappa = out;          // [32]
    float* cond  = out + B_SZ;   // [32,100,100]

    const int SMEM_JAC = (2 * BUFW + 32) * sizeof(float);  // ~153.7 KB
    cudaFuncSetAttribute(jacobi_kernel, cudaFuncAttributeMaxDynamicSharedMemorySize, SMEM_JAC);

    fc1_kernel<<<(B_SZ * 128 + 255) / 256, 256>>>(pores, W1, b1);
    fc2_kernel<<<(B_SZ * 256 + 255) / 256, 256>>>(W2, b2);
    fc3_kernel<<<(B_SZ * 512 + 255) / 256, 256>>>(W3, b3);
    dim3 g4((10000 + 127) / 128, KSPLIT);
    fc4_partial_kernel<<<g4, 128>>>(W4);
    dim3 g5((10000 + 127) / 128, B_SZ / 4);
    fc4_final_kernel<<<g5, 128>>>(b4, pores, cond);
    jacobi_kernel<<<B_SZ, 400, SMEM_JAC>>>(cond, kappa);
}

// round 8
// speedup vs baseline: 1.8509x; 1.8509x over previous
#include <cuda_runtime.h>
#include <cstdint>

#define B_SZ   32
#define RESN   100
#define ITERS  1000
#define KSPLIT 16

typedef unsigned long long ull;

// Jacobi: 250 threads, each owns 4 rows x 10 cols in registers.
// SMEM per buffer (words): TOP 3000 | BOT 3000 | CL 1000 | CR 1000 = 8000
#define SLOTW  12
#define OFF_BOT 3000
#define OFF_CL  6000
#define OFF_CR  7000
#define BUFW    8000

// -------- scratch (device globals; no allocation allowed) ----------
__device__ float g_h1[B_SZ * 128];
__device__ float g_h2[B_SZ * 256];
__device__ float g_h3[B_SZ * 512];
__device__ float g_part[KSPLIT * B_SZ * 10000];

// ---------------------- f32x2 helpers ------------------------------
__device__ __forceinline__ ull pack2(float lo, float hi) {
    ull r; unsigned a = __float_as_uint(lo), b = __float_as_uint(hi);
    asm("mov.b64 %0, {%1,%2};" : "=l"(r) : "r"(a), "r"(b));
    return r;
}
__device__ __forceinline__ float lo2(ull v) {
    unsigned a, b;
    asm("mov.b64 {%0,%1}, %2;" : "=r"(a), "=r"(b) : "l"(v));
    return __uint_as_float(a);
}
__device__ __forceinline__ float hi2(ull v) {
    unsigned a, b;
    asm("mov.b64 {%0,%1}, %2;" : "=r"(a), "=r"(b) : "l"(v));
    return __uint_as_float(b);
}
__device__ __forceinline__ ull shift_pair(ull a, ull b) {   // (hi a, lo b)
    unsigned a0, a1, b0, b1;
    asm("mov.b64 {%0,%1}, %2;" : "=r"(a0), "=r"(a1) : "l"(a));
    asm("mov.b64 {%0,%1}, %2;" : "=r"(b0), "=r"(b1) : "l"(b));
    ull r;
    asm("mov.b64 %0, {%1,%2};" : "=l"(r) : "r"(a1), "r"(b0));
    return r;
}
__device__ __forceinline__ ull fma2(ull a, ull b, ull c) {
    ull d;
    asm("fma.rn.f32x2 %0, %1, %2, %3;" : "=l"(d) : "l"(a), "l"(b), "l"(c));
    return d;
}
__device__ __forceinline__ ull mul2(ull a, ull b) {
    ull d;
    asm("mul.rn.f32x2 %0, %1, %2;" : "=l"(d) : "l"(a), "l"(b));
    return d;
}

// -------------------- MLP layers 1..3 (small) ----------------------
__global__ void fc1_kernel(const float* __restrict__ pores,
                           const float* __restrict__ W,
                           const float* __restrict__ bias) {
    int idx = blockIdx.x * blockDim.x + threadIdx.x;
    if (idx >= B_SZ * 128) return;
    int b = idx >> 7, j = idx & 127;
    float acc = bias[j];
#pragma unroll
    for (int k = 0; k < 25; k++)
        acc = fmaf(pores[b * 25 + k], W[k * 128 + j], acc);
    g_h1[idx] = fmaxf(acc, 0.0f);
}

__global__ void fc2_kernel(const float* __restrict__ W,
                           const float* __restrict__ bias) {
    int idx = blockIdx.x * blockDim.x + threadIdx.x;
    if (idx >= B_SZ * 256) return;
    int b = idx >> 8, j = idx & 255;
    float acc = bias[j];
#pragma unroll 8
    for (int k = 0; k < 128; k++)
        acc = fmaf(g_h1[b * 128 + k], W[k * 256 + j], acc);
    g_h2[idx] = fmaxf(acc, 0.0f);
}

__global__ void fc3_kernel(const float* __restrict__ W,
                           const float* __restrict__ bias) {
    int idx = blockIdx.x * blockDim.x + threadIdx.x;
    if (idx >= B_SZ * 512) return;
    int b = idx >> 9, j = idx & 511;
    float acc = bias[j];
#pragma unroll 8
    for (int k = 0; k < 256; k++)
        acc = fmaf(g_h2[b * 256 + k], W[k * 512 + j], acc);
    g_h3[idx] = fmaxf(acc, 0.0f);
}

// ---------------- fc4 stage 1: split-K partial sums ----------------
__global__ __launch_bounds__(128) void fc4_partial_kernel(
    const float* __restrict__ W)     // [512,10000]
{
    __shared__ float h3s[B_SZ * 32];
    int k0 = blockIdx.y * 32;
    for (int i = threadIdx.x; i < B_SZ * 32; i += blockDim.x) {
        int q = i >> 5, kk = i & 31;
        h3s[i] = g_h3[q * 512 + k0 + kk];
    }
    __syncthreads();

    int o = blockIdx.x * blockDim.x + threadIdx.x;
    if (o >= RESN * RESN) return;

    float acc[B_SZ];
#pragma unroll
    for (int q = 0; q < B_SZ; q++) acc[q] = 0.0f;

#pragma unroll
    for (int kk = 0; kk < 32; kk += 4) {
        float w0 = W[(k0 + kk + 0) * 10000 + o];
        float w1 = W[(k0 + kk + 1) * 10000 + o];
        float w2 = W[(k0 + kk + 2) * 10000 + o];
        float w3 = W[(k0 + kk + 3) * 10000 + o];
#pragma unroll
        for (int q = 0; q < B_SZ; q++) {
            acc[q] = fmaf(h3s[q * 32 + kk + 0], w0, acc[q]);
            acc[q] = fmaf(h3s[q * 32 + kk + 1], w1, acc[q]);
            acc[q] = fmaf(h3s[q * 32 + kk + 2], w2, acc[q]);
            acc[q] = fmaf(h3s[q * 32 + kk + 3], w3, acc[q]);
        }
    }

    float* dst = g_part + blockIdx.y * (B_SZ * 10000);
#pragma unroll
    for (int q = 0; q < B_SZ; q++)
        dst[q * 10000 + o] = acc[q];
}

// -------- fc4 stage 2: reduce + bias + residual + clamp ------------
__global__ __launch_bounds__(128) void fc4_final_kernel(
    const float* __restrict__ bias,
    const float* __restrict__ pores,
    float* __restrict__ cond)
{
    int o = blockIdx.x * blockDim.x + threadIdx.x;
    if (o >= RESN * RESN) return;
    int i = o / RESN, j = o % RESN;
    int pidx = (i / 20) * 5 + (j / 20);
    float bb = bias[o];
    int q0 = blockIdx.y * 4;
#pragma unroll
    for (int qq = 0; qq < 4; qq++) {
        int q = q0 + qq;
        float s = bb;
#pragma unroll
        for (int p = 0; p < KSPLIT; p++)
            s += g_part[p * (B_SZ * 10000) + q * 10000 + o];
        float base = 1.0f - pores[q * 25 + pidx];
        cond[q * 10000 + o] = fmaxf(s + base, 0.01f);
    }
}

// ---------- Jacobi: 4x10 register tiles, 250 threads ----------------
// band = tid/10 (25 bands of 4 rows), tcol = tid%10 (10 strips of 10 cols).
// T tile P[4][5] as f32x2 pairs. Per iter only the perimeter moves
// through SMEM: top row, bottom row (12-word slots, 48B stride ->
// conflict-free), left col, right col (dense float4 arrays).
__global__ __launch_bounds__(256, 1)
void jacobi_kernel(const float* __restrict__ cond,   // [32,10000]
                   float* __restrict__ kappa)        // [32]
{
    extern __shared__ float sm[];
    float* partial = sm + 2 * BUFW;    // 10 floats

    int b = blockIdx.x;
    const float* k = cond + b * 10000;
    int tid  = threadIdx.x;            // 0..249, all active
    int band = tid / 10;               // 0..24
    int tcol = tid % 10;               // 0..9
    int r0 = band * 4, c0 = tcol * 10;

    const ull ONE2 = 0x3F8000003F800000ULL;

    ull cN[4][5], cS[4][5], cW[4][5], cE[4][5], P[4][5];

    // ---- coefficients (registers, computed once) ----
#pragma unroll
    for (int i = 0; i < 4; i++) {
        int rg = r0 + i;
        int rm = (rg == 0)  ? 0  : rg - 1;
        int rp = (rg == 99) ? 99 : rg + 1;
        float fN[10], fS[10], fW[10], fE[10];
#pragma unroll
        for (int j = 0; j < 10; j++) {
            int c  = c0 + j;
            int cm = (c == 0)  ? 0  : c - 1;
            int cp = (c == 99) ? 99 : c + 1;
            float kc = k[rg * 100 + c];
            float kn = 0.5f * (kc + k[rm * 100 + c]);
            float ks = 0.5f * (kc + k[rp * 100 + c]);
            float kw = 0.5f * (kc + k[rg * 100 + cm]);
            float ke = 0.5f * (kc + k[rg * 100 + cp]);
            float inv = 1.0f / (kn + ks + kw + ke + 1e-12f);
            fN[j] = kn * inv; fS[j] = ks * inv;
            fW[j] = kw * inv; fE[j] = ke * inv;
        }
#pragma unroll
        for (int p = 0; p < 5; p++) {
            cN[i][p] = pack2(fN[2*p], fN[2*p+1]);
            cS[i][p] = pack2(fS[2*p], fS[2*p+1]);
            cW[i][p] = pack2(fW[2*p], fW[2*p+1]);
            cE[i][p] = pack2(fE[2*p], fE[2*p+1]);
        }
    }

    // ---- initial field + buffer-0 perimeter ----
#pragma unroll
    for (int i = 0; i < 4; i++) {
        float tv = 1.0f - (float)(r0 + i) * (1.0f / 99.0f);
#pragma unroll
        for (int p = 0; p < 5; p++) P[i][p] = pack2(tv, tv);
    }
    {
        float* tp = sm + tid * SLOTW;
        ulonglong2 v; v.x = P[0][0]; v.y = P[0][1];
        *reinterpret_cast<ulonglong2*>(tp) = v;
        v.x = P[0][2]; v.y = P[0][3];
        *reinterpret_cast<ulonglong2*>(tp + 4) = v;
        *reinterpret_cast<ull*>(tp + 8) = P[0][4];
        float* bt = sm + OFF_BOT + tid * SLOTW;
        v.x = P[3][0]; v.y = P[3][1];
        *reinterpret_cast<ulonglong2*>(bt) = v;
        v.x = P[3][2]; v.y = P[3][3];
        *reinterpret_cast<ulonglong2*>(bt + 4) = v;
        *reinterpret_cast<ull*>(bt + 8) = P[3][4];
        *reinterpret_cast<float4*>(sm + OFF_CL + tid * 4) =
            make_float4(lo2(P[0][0]), lo2(P[1][0]), lo2(P[2][0]), lo2(P[3][0]));
        *reinterpret_cast<float4*>(sm + OFF_CR + tid * 4) =
            make_float4(hi2(P[0][4]), hi2(P[1][4]), hi2(P[2][4]), hi2(P[3][4]));
    }
    __syncthreads();

    int cur = 0;
    for (int it = 0; it < ITERS; ++it) {
        const float* C  = sm + cur * BUFW;
        float*       Nx = sm + (cur ^ 1) * BUFW;

        // ---- halo loads (OLD values; clamp addr, override value) ----
        const float* np = C + OFF_BOT + ((band == 0)  ? tid : tid - 10) * SLOTW;
        const float* sp = C +            ((band == 24) ? tid : tid + 10) * SLOTW;
        ulonglong2 nA = *reinterpret_cast<const ulonglong2*>(np);
        ulonglong2 nB = *reinterpret_cast<const ulonglong2*>(np + 4);
        ull        nC = *reinterpret_cast<const ull*>(np + 8);
        ulonglong2 sA = *reinterpret_cast<const ulonglong2*>(sp);
        ulonglong2 sB = *reinterpret_cast<const ulonglong2*>(sp + 4);
        ull        sC = *reinterpret_cast<const ull*>(sp + 8);
        float4 wf = *reinterpret_cast<const float4*>(
            C + OFF_CR + ((tcol == 0) ? tid : tid - 1) * 4);
        float4 ef = *reinterpret_cast<const float4*>(
            C + OFF_CL + ((tcol == 9) ? tid : tid + 1) * 4);

        if (band == 0)  { nA.x = ONE2; nA.y = ONE2; nB.x = ONE2; nB.y = ONE2; nC = ONE2; }
        if (band == 24) { sA.x = 0; sA.y = 0; sB.x = 0; sB.y = 0; sC = 0; }
        float west[4] = {wf.x, wf.y, wf.z, wf.w};
        float east[4] = {ef.x, ef.y, ef.z, ef.w};

        ull pn0 = nA.x, pn1 = nA.y, pn2 = nB.x, pn3 = nB.y, pn4 = nC;
#pragma unroll
        for (int i = 0; i < 4; i++) {
            ull o0 = P[i][0], o1 = P[i][1], o2 = P[i][2], o3 = P[i][3], o4 = P[i][4];
            ull s0, s1, s2, s3, s4;
            if (i < 3) { s0 = P[i+1][0]; s1 = P[i+1][1]; s2 = P[i+1][2];
                         s3 = P[i+1][3]; s4 = P[i+1][4]; }
            else       { s0 = sA.x; s1 = sA.y; s2 = sB.x; s3 = sB.y; s4 = sC; }

            float left  = (tcol == 0) ? lo2(o0) : west[i];
            float right = (tcol == 9) ? hi2(o4) : east[i];

            ull W0 = pack2(left, lo2(o0));
            ull E0 = shift_pair(o0, o1);
            ull E1 = shift_pair(o1, o2);
            ull E2 = shift_pair(o2, o3);
            ull E3 = shift_pair(o3, o4);
            ull E4 = pack2(hi2(o4), right);

            P[i][0] = fma2(cN[i][0], pn0, fma2(cS[i][0], s0,
                      fma2(cW[i][0], W0, mul2(cE[i][0], E0))));
            P[i][1] = fma2(cN[i][1], pn1, fma2(cS[i][1], s1,
                      fma2(cW[i][1], E0, mul2(cE[i][1], E1))));
            P[i][2] = fma2(cN[i][2], pn2, fma2(cS[i][2], s2,
                      fma2(cW[i][2], E1, mul2(cE[i][2], E2))));
            P[i][3] = fma2(cN[i][3], pn3, fma2(cS[i][3], s3,
                      fma2(cW[i][3], E2, mul2(cE[i][3], E3))));
            P[i][4] = fma2(cN[i][4], pn4, fma2(cS[i][4], s4,
                      fma2(cW[i][4], E3, mul2(cE[i][4], E4))));

            pn0 = o0; pn1 = o1; pn2 = o2; pn3 = o3; pn4 = o4;
        }

        // ---- publish new perimeter ----
        float* tp = Nx + tid * SLOTW;
        ulonglong2 v; v.x = P[0][0]; v.y = P[0][1];
        *reinterpret_cast<ulonglong2*>(tp) = v;
        v.x = P[0][2]; v.y = P[0][3];
        *reinterpret_cast<ulonglong2*>(tp + 4) = v;
        *reinterpret_cast<ull*>(tp + 8) = P[0][4];
        float* bt = Nx + OFF_BOT + tid * SLOTW;
        v.x = P[3][0]; v.y = P[3][1];
        *reinterpret_cast<ulonglong2*>(bt) = v;
        v.x = P[3][2]; v.y = P[3][3];
        *reinterpret_cast<ulonglong2*>(bt + 4) = v;
        *reinterpret_cast<ull*>(bt + 8) = P[3][4];
        *reinterpret_cast<float4*>(Nx + OFF_CL + tid * 4) =
            make_float4(lo2(P[0][0]), lo2(P[1][0]), lo2(P[2][0]), lo2(P[3][0]));
        *reinterpret_cast<float4*>(Nx + OFF_CR + tid * 4) =
            make_float4(hi2(P[0][4]), hi2(P[1][4]), hi2(P[2][4]), hi2(P[3][4]));

        __syncthreads();
        cur ^= 1;
    }

    // kappa = 2 * sum_c k[0,c] * (1 - T[0,c]); band 0 holds global row 0
    if (band == 0) {
        float p = 0.0f;
#pragma unroll
        for (int m = 0; m < 5; m++) {
            p += k[c0 + 2*m]     * (1.0f - lo2(P[0][m]));
            p += k[c0 + 2*m + 1] * (1.0f - hi2(P[0][m]));
        }
        partial[tcol] = p;
    }
    __syncthreads();
    if (tid == 0) {
        float sum = 0.0f;
#pragma unroll
        for (int q = 0; q < 10; q++) sum += partial[q];
        kappa[b] = 2.0f * sum;
    }
}

// --------------------------- launcher ------------------------------
extern "C" void kernel_launch(void* const* d_in, const int* in_sizes, int n_in,
                              void* d_out, int out_size) {
    const float* pores = (const float*)d_in[0];
    const float* W1 = (const float*)d_in[1];
    const float* b1 = (const float*)d_in[2];
    const float* W2 = (const float*)d_in[3];
    const float* b2 = (const float*)d_in[4];
    const float* W3 = (const float*)d_in[5];
    const float* b3 = (const float*)d_in[6];
    const float* W4 = (const float*)d_in[7];
    const float* b4 = (const float*)d_in[8];

    float* out   = (float*)d_out;
    float* kappa = out;          // [32]
    float* cond  = out + B_SZ;   // [32,100,100]

    const int SMEM_JAC = (2 * BUFW + 16) * sizeof(float);  // ~64.1 KB
    cudaFuncSetAttribute(jacobi_kernel, cudaFuncAttributeMaxDynamicSharedMemorySize, SMEM_JAC);

    fc1_kernel<<<(B_SZ * 128 + 255) / 256, 256>>>(pores, W1, b1);
    fc2_kernel<<<(B_SZ * 256 + 255) / 256, 256>>>(W2, b2);
    fc3_kernel<<<(B_SZ * 512 + 255) / 256, 256>>>(W3, b3);
    dim3 g4((10000 + 127) / 128, KSPLIT);
    fc4_partial_kernel<<<g4, 128>>>(W4);
    dim3 g5((10000 + 127) / 128, B_SZ / 4);
    fc4_final_kernel<<<g5, 128>>>(b4, pores, cond);
    jacobi_kernel<<<B_SZ, 250, SMEM_JAC>>>(cond, kappa);
}